// round 3
// baseline (speedup 1.0000x reference)
#include <cuda_runtime.h>

// EKF cell: B=262144, N=8, M=4. One thread per batch.
// Round-3 changes:
//  * cp.async prefetch of H / process_noise / measurement_noise into smem at t=0
//    (warp-cooperative, coalesced 16B chunks) -> all DRAM latency overlapped
//    with the predict-phase compute instead of exposed mid-kernel.
//  * P' = F P F^T computed column-strip-wise (no 64-reg G intermediate).
//  * Symmetric-matrix tri compression as in round 2.

__device__ __forceinline__ float psym(const float* t, int i, int j) {
    return (i >= j) ? t[i*(i+1)/2 + j] : t[j*(j+1)/2 + i];
}

__device__ __forceinline__ void cp16(void* smem_dst, const void* gmem_src) {
    unsigned s = (unsigned)__cvta_generic_to_shared(smem_dst);
    asm volatile("cp.async.cg.shared.global [%0], [%1], 16;\n"
                 :: "r"(s), "l"(gmem_src) : "memory");
}

// smem per warp (floats): H 32*36 (128B data + 16B pad per batch), pn 32*36, mn 32*10
#define SM_H_W   1152
#define SM_PN_W  1152
#define SM_MN_W  320
#define SM_WARP_W (SM_H_W + SM_PN_W + SM_MN_W)   // 2624 floats = 10496 B

__global__ __launch_bounds__(128, 3) void ekf_kernel(
    const float* __restrict__ g_meas,
    const float* __restrict__ g_state,
    const float* __restrict__ g_cov,
    const float* __restrict__ g_F,
    const float* __restrict__ g_H,
    const float* __restrict__ g_pn,
    const float* __restrict__ g_mn,
    float* __restrict__ o_pred,
    float* __restrict__ o_state,
    float* __restrict__ o_cov,
    int B)
{
    __shared__ float sm[4 * SM_WARP_W];

    const int tid  = threadIdx.x;
    const int w    = tid >> 5;
    const int lane = tid & 31;
    const int b    = blockIdx.x * 128 + tid;
    const int warpBatch0 = blockIdx.x * 128 + w * 32;

    float* smH  = sm + w * SM_WARP_W;
    float* smPN = smH + SM_H_W;
    float* smMN = smPN + SM_PN_W;

    // ---------- cp.async prefetch (warp-cooperative, coalesced) ----------
    {
        const int validB = (warpBatch0 + 32 <= B) ? 32 : (B > warpBatch0 ? B - warpBatch0 : 0);
        const char* gH  = (const char*)g_H  + (size_t)warpBatch0 * 128;
        const char* gPN = (const char*)g_pn + (size_t)warpBatch0 * 144;
        const char* gMN = (const char*)g_mn + (size_t)warpBatch0 * 40;

        // H: 32 batches x 128B = 256 chunks; smem stride 144B/batch (pad 16B)
        #pragma unroll
        for (int i = 0; i < 8; i++) {
            int g = lane + 32 * i;
            if (g < validB * 8)
                cp16(smH + ((g >> 3) * 36 + (g & 7) * 4), gH + g * 16);
        }
        // pn: 32 x 144B = 288 chunks; linear (stride already 36 words)
        #pragma unroll
        for (int i = 0; i < 9; i++) {
            int g = lane + 32 * i;
            if (g < validB * 9)
                cp16(smPN + g * 4, gPN + g * 16);
        }
        // mn: 32 x 40B = 1280B = 80 chunks; linear
        #pragma unroll
        for (int i = 0; i < 3; i++) {
            int g = lane + 32 * i;
            if (g * 16 < validB * 40)
                cp16(smMN + g * 4, gMN + g * 16);
        }
        asm volatile("cp.async.commit_group;\n" ::: "memory");
    }

    if (b >= B) {  // keep warp converged through the wait, then exit
        asm volatile("cp.async.wait_group 0;\n" ::: "memory");
        __syncwarp();
        return;
    }

    // ---------- per-thread LDGs (all issued up front by the compiler) ----------
    float Fm[64];
    {
        const float4* f4 = reinterpret_cast<const float4*>(g_F) + (size_t)b * 16;
        #pragma unroll
        for (int v = 0; v < 16; v++) {
            float4 x = f4[v];
            Fm[4*v+0] = x.x; Fm[4*v+1] = x.y; Fm[4*v+2] = x.z; Fm[4*v+3] = x.w;
        }
    }
    float Pt[36];
    {
        const float4* p4 = reinterpret_cast<const float4*>(g_cov) + (size_t)b * 16;
        #pragma unroll
        for (int v = 0; v < 16; v++) {
            float4 x = p4[v];
            float vals[4] = {x.x, x.y, x.z, x.w};
            #pragma unroll
            for (int c = 0; c < 4; c++) {
                int e = 4*v + c, i = e >> 3, j = e & 7;
                if (i >= j) Pt[i*(i+1)/2 + j] = vals[c];
            }
        }
    }
    float mea[4];
    {
        float4 mv = reinterpret_cast<const float4*>(g_meas)[b];
        mea[0] = mv.x; mea[1] = mv.y; mea[2] = mv.z; mea[3] = mv.w;
    }

    // ---- new_state = F @ state ----
    float ns[8];
    {
        const float4* s4 = reinterpret_cast<const float4*>(g_state) + (size_t)b * 2;
        float4 a = s4[0], c = s4[1];
        float st[8] = {a.x, a.y, a.z, a.w, c.x, c.y, c.z, c.w};
        #pragma unroll
        for (int i = 0; i < 8; i++) {
            float acc = 0.f;
            #pragma unroll
            for (int j = 0; j < 8; j++) acc += Fm[i*8+j] * st[j];
            ns[i] = acc;
        }
    }

    // ---- P' = F P F^T, column-strip (no full G intermediate), lower tri ----
    float Pp[36];
    #pragma unroll
    for (int l = 0; l < 8; l++) {
        float g[8];
        #pragma unroll
        for (int j = 0; j < 8; j++) {
            float a = 0.f;
            #pragma unroll
            for (int k = 0; k < 8; k++) a += psym(Pt, j, k) * Fm[l*8+k];
            g[j] = a;
        }
        #pragma unroll
        for (int i = l; i < 8; i++) {
            float a = 0.f;
            #pragma unroll
            for (int j = 0; j < 8; j++) a += Fm[i*8+j] * g[j];
            Pp[i*(i+1)/2 + l] = a;
        }
    }
    // Fm, Pt dead.

    // ---------- consume prefetched data ----------
    asm volatile("cp.async.wait_group 0;\n" ::: "memory");
    __syncwarp();

    // ---- P' += Q = Lq Lq^T ----
    {
        float Lq[36];
        const float4* q4 = reinterpret_cast<const float4*>(smPN + lane * 36);
        #pragma unroll
        for (int v = 0; v < 9; v++) {
            float4 x = q4[v];
            Lq[4*v+0] = x.x; Lq[4*v+1] = x.y; Lq[4*v+2] = x.z; Lq[4*v+3] = x.w;
        }
        #pragma unroll
        for (int i = 0; i < 8; i++) {
            #pragma unroll
            for (int l = 0; l <= i; l++) {
                float a = Pp[i*(i+1)/2 + l];
                #pragma unroll
                for (int k = 0; k <= l; k++)
                    a += Lq[i*(i+1)/2 + k] * Lq[l*(l+1)/2 + k];
                Pp[i*(i+1)/2 + l] = a;
            }
        }
    }

    // ---- H from smem; prediction & residual ----
    float Hm[32];
    {
        const float4* h4 = reinterpret_cast<const float4*>(smH + lane * 36);
        #pragma unroll
        for (int v = 0; v < 8; v++) {
            float4 x = h4[v];
            Hm[4*v+0] = x.x; Hm[4*v+1] = x.y; Hm[4*v+2] = x.z; Hm[4*v+3] = x.w;
        }
    }
    float pred[4], res[4];
    #pragma unroll
    for (int i = 0; i < 4; i++) {
        float a = 0.f;
        #pragma unroll
        for (int j = 0; j < 8; j++) a += Hm[i*8+j] * ns[j];
        pred[i] = a;
        res[i] = mea[i] - a;
    }

    // ---- PHt = P' @ H^T  (8x4) ----
    float PHt[32];
    #pragma unroll
    for (int i = 0; i < 8; i++) {
        #pragma unroll
        for (int j = 0; j < 4; j++) {
            float a = 0.f;
            #pragma unroll
            for (int k = 0; k < 8; k++) a += psym(Pp, i, k) * Hm[j*8+k];
            PHt[i*4+j] = a;
        }
    }

    // ---- S = H @ PHt + R  (4x4 SPD) ----
    float A[16];
    {
        float Lr[10];
        const float2* r2 = reinterpret_cast<const float2*>(smMN + lane * 10);
        #pragma unroll
        for (int i = 0; i < 5; i++) { float2 v = r2[i]; Lr[2*i] = v.x; Lr[2*i+1] = v.y; }
        #pragma unroll
        for (int i = 0; i < 4; i++) {
            #pragma unroll
            for (int j = 0; j < 4; j++) {
                float a = 0.f;
                #pragma unroll
                for (int k = 0; k <= ((i < j) ? i : j); k++)
                    a += Lr[i*(i+1)/2 + k] * Lr[j*(j+1)/2 + k];
                #pragma unroll
                for (int k = 0; k < 8; k++) a += Hm[i*8+k] * PHt[k*4+j];
                A[i*4+j] = a;
            }
        }
    }
    // Hm dead (epilogue uses the symmetry identity H P' = PHt^T).

    // ---- Solve S X = [PHt^T | res]  (Gauss-Jordan, pivot-free: S SPD) ----
    float Rh[36];
    #pragma unroll
    for (int r = 0; r < 4; r++) {
        #pragma unroll
        for (int c = 0; c < 8; c++) Rh[r*9+c] = PHt[c*4+r];
        Rh[r*9+8] = res[r];
    }
    #pragma unroll
    for (int c = 0; c < 4; c++) {
        float inv = 1.0f / A[c*4+c];
        #pragma unroll
        for (int j = 0; j < 4; j++) A[c*4+j] *= inv;
        #pragma unroll
        for (int j = 0; j < 9; j++) Rh[c*9+j] *= inv;
        #pragma unroll
        for (int r = 0; r < 4; r++) {
            if (r == c) continue;
            float f = A[r*4+c];
            #pragma unroll
            for (int j = 0; j < 4; j++) A[r*4+j] -= f * A[c*4+j];
            #pragma unroll
            for (int j = 0; j < 9; j++) Rh[r*9+j] -= f * Rh[c*9+j];
        }
    }

    // ---- upd_state = ns + PHt @ z ----
    float us[8];
    #pragma unroll
    for (int i = 0; i < 8; i++) {
        float a = ns[i];
        #pragma unroll
        for (int j = 0; j < 4; j++) a += PHt[i*4+j] * Rh[j*9+8];
        us[i] = a;
    }

    // ---- stores ----
    reinterpret_cast<float4*>(o_pred)[b] = make_float4(pred[0], pred[1], pred[2], pred[3]);
    {
        float4* s4 = reinterpret_cast<float4*>(o_state) + (size_t)b * 2;
        s4[0] = make_float4(us[0], us[1], us[2], us[3]);
        s4[1] = make_float4(us[4], us[5], us[6], us[7]);
    }

    // ---- upd_cov = P' - PHt X  (symmetric; compute tri, mirror at store) ----
    float UC[36];
    #pragma unroll
    for (int i = 0; i < 8; i++) {
        #pragma unroll
        for (int l = 0; l <= i; l++) {
            float a = Pp[i*(i+1)/2 + l];
            #pragma unroll
            for (int j = 0; j < 4; j++) a -= PHt[i*4+j] * Rh[j*9+l];
            UC[i*(i+1)/2 + l] = a;
        }
    }
    float4* c4 = reinterpret_cast<float4*>(o_cov) + (size_t)b * 16;
    #pragma unroll
    for (int i = 0; i < 8; i++) {
        c4[i*2+0] = make_float4(psym(UC,i,0), psym(UC,i,1), psym(UC,i,2), psym(UC,i,3));
        c4[i*2+1] = make_float4(psym(UC,i,4), psym(UC,i,5), psym(UC,i,6), psym(UC,i,7));
    }
}

extern "C" void kernel_launch(void* const* d_in, const int* in_sizes, int n_in,
                              void* d_out, int out_size)
{
    const float* g_meas = (const float*)d_in[0];
    const float* g_state = (const float*)d_in[1];
    const float* g_cov  = (const float*)d_in[2];
    const float* g_F    = (const float*)d_in[3];
    const float* g_H    = (const float*)d_in[4];
    const float* g_pn   = (const float*)d_in[5];
    const float* g_mn   = (const float*)d_in[6];

    int B = in_sizes[0] / 4;   // measurement is (B, 4)

    float* o_pred  = (float*)d_out;
    float* o_state = o_pred + (size_t)B * 4;
    float* o_cov   = o_state + (size_t)B * 8;

    int threads = 128;
    int blocks = (B + threads - 1) / threads;
    ekf_kernel<<<blocks, threads>>>(g_meas, g_state, g_cov, g_F, g_H, g_pn, g_mn,
                                    o_pred, o_state, o_cov, B);
}

// round 4
// speedup vs baseline: 1.1414x; 1.1414x over previous
#include <cuda_runtime.h>

// EKF cell: B=262144, N=8, M=4. One thread per batch, one warp per 32-batch CTA.
// Round-4: all strided global traffic replaced by cp.async.bulk DMA into smem
// (loads) and out of smem (cov store), with in-place pad-repack (stride 16->17
// float4) so smem->register transposes are bank-conflict-free with static
// register indexing.

#define OFF_F   0        // 2176 floats (544 f4): F, padded stride 17 f4
#define OFF_P   2176     // 2176 floats: state_cov, padded stride 17 f4
#define OFF_H   4352     // 1152 floats (288 f4): H, padded stride 9 f4
#define OFF_PN  5504     // 1152 floats: process noise, natural stride 9 f4
#define OFF_MN  6656     // 320 floats: measurement noise, natural stride 5 f2
#define OFF_MB  6976     // mbarrier (8B)
#define SM_FLOATS 6980
#define TX_BYTES 26368u  // 8192+8192+4096+4608+1280

__device__ __forceinline__ float psym(const float* t, int i, int j) {
    return (i >= j) ? t[i*(i+1)/2 + j] : t[j*(j+1)/2 + i];
}

__device__ __forceinline__ unsigned sptr(const void* p) {
    return (unsigned)__cvta_generic_to_shared(p);
}

__device__ __forceinline__ void bulk_g2s(unsigned dst, const void* src,
                                         unsigned bytes, unsigned mbar) {
    asm volatile(
        "cp.async.bulk.shared::cluster.global.mbarrier::complete_tx::bytes [%0], [%1], %2, [%3];"
        :: "r"(dst), "l"(src), "r"(bytes), "r"(mbar) : "memory");
}

__device__ __forceinline__ void bulk_s2g(void* dst, unsigned src, unsigned bytes) {
    asm volatile(
        "cp.async.bulk.global.shared::cta.bulk_group [%0], [%1], %2;"
        :: "l"(dst), "r"(src), "r"(bytes) : "memory");
}

__global__ __launch_bounds__(32, 8) void ekf_kernel(
    const float* __restrict__ g_meas,
    const float* __restrict__ g_state,
    const float* __restrict__ g_cov,
    const float* __restrict__ g_F,
    const float* __restrict__ g_H,
    const float* __restrict__ g_pn,
    const float* __restrict__ g_mn,
    float* __restrict__ o_pred,
    float* __restrict__ o_state,
    float* __restrict__ o_cov,
    int B)
{
    __shared__ __align__(16) float sm[SM_FLOATS];
    float4* s4m = reinterpret_cast<float4*>(sm);

    const int lane = threadIdx.x;
    int wb = blockIdx.x * 32;
    if (wb + 32 > B) wb = B - 32;   // clamp: duplicate identical work, in-bounds
    const int b = wb + lane;

    const unsigned smb  = sptr(sm);
    const unsigned mbar = smb + OFF_MB * 4;

    // ---------- bulk DMA loads ----------
    if (lane == 0) {
        asm volatile("mbarrier.init.shared.b64 [%0], 1;" :: "r"(mbar) : "memory");
    }
    __syncwarp();
    if (lane == 0) {
        asm volatile("fence.proxy.async.shared::cta;" ::: "memory");
        asm volatile("mbarrier.arrive.expect_tx.shared.b64 _, [%0], %1;"
                     :: "r"(mbar), "r"(TX_BYTES) : "memory");
        bulk_g2s(smb + OFF_F  * 4, g_F   + (size_t)wb * 64, 8192, mbar);
        bulk_g2s(smb + OFF_P  * 4, g_cov + (size_t)wb * 64, 8192, mbar);
        bulk_g2s(smb + OFF_H  * 4, g_H   + (size_t)wb * 32, 4096, mbar);
        bulk_g2s(smb + OFF_PN * 4, g_pn  + (size_t)wb * 36, 4608, mbar);
        bulk_g2s(smb + OFF_MN * 4, g_mn  + (size_t)wb * 10, 1280, mbar);
    }

    // overlap the DMA with the (already coalesced-enough) small direct loads
    float mea[4], st[8];
    {
        float4 mv = reinterpret_cast<const float4*>(g_meas)[b];
        mea[0] = mv.x; mea[1] = mv.y; mea[2] = mv.z; mea[3] = mv.w;
        const float4* s4 = reinterpret_cast<const float4*>(g_state) + (size_t)b * 2;
        float4 a = s4[0], c = s4[1];
        st[0]=a.x; st[1]=a.y; st[2]=a.z; st[3]=a.w;
        st[4]=c.x; st[5]=c.y; st[6]=c.z; st[7]=c.w;
    }

    // wait for DMA
    {
        asm volatile(
            "{\n\t"
            ".reg .pred P;\n"
            "W%=:\n\t"
            "mbarrier.try_wait.parity.shared.b64 P, [%0], 0;\n\t"
            "@!P bra W%=;\n\t"
            "}"
            :: "r"(mbar) : "memory");
    }
    __syncwarp();

    // ---------- in-place pad-repack: F and P, stride 16 -> 17 float4 ----------
    #pragma unroll
    for (int base = 544; base >= 0; base -= 544) {   // base 544 = P, base 0 = F
        float4 t[8];
        // pass A: batches 16..31
        #pragma unroll
        for (int k = 0; k < 8; k++) t[k] = s4m[base + 256 + lane + 32*k];
        __syncwarp();
        #pragma unroll
        for (int k = 0; k < 8; k++) {
            int g = 256 + lane + 32*k;
            s4m[base + (g >> 4) * 17 + (g & 15)] = t[k];
        }
        __syncwarp();
        // pass B: batches 0..15
        #pragma unroll
        for (int k = 0; k < 8; k++) t[k] = s4m[base + lane + 32*k];
        __syncwarp();
        #pragma unroll
        for (int k = 0; k < 8; k++) {
            int g = lane + 32*k;
            s4m[base + (g >> 4) * 17 + (g & 15)] = t[k];
        }
        __syncwarp();
    }
    // H: stride 8 -> 9 float4 (base f4 = 1088)
    {
        float4 t[4];
        #pragma unroll
        for (int k = 0; k < 4; k++) t[k] = s4m[1088 + 128 + lane + 32*k];
        __syncwarp();
        #pragma unroll
        for (int k = 0; k < 4; k++) {
            int g = 128 + lane + 32*k;
            s4m[1088 + (g >> 3) * 9 + (g & 7)] = t[k];
        }
        __syncwarp();
        #pragma unroll
        for (int k = 0; k < 4; k++) t[k] = s4m[1088 + lane + 32*k];
        __syncwarp();
        #pragma unroll
        for (int k = 0; k < 4; k++) {
            int g = lane + 32*k;
            s4m[1088 + (g >> 3) * 9 + (g & 7)] = t[k];
        }
        __syncwarp();
    }

    // ---------- unpack F (64) and P (tri 36); banks conflict-free ----------
    float Fm[64];
    #pragma unroll
    for (int v = 0; v < 16; v++) {
        float4 x = s4m[lane * 17 + v];
        Fm[4*v+0] = x.x; Fm[4*v+1] = x.y; Fm[4*v+2] = x.z; Fm[4*v+3] = x.w;
    }
    float Pt[36];
    #pragma unroll
    for (int v = 0; v < 16; v++) {
        float4 x = s4m[544 + lane * 17 + v];
        float vals[4] = {x.x, x.y, x.z, x.w};
        #pragma unroll
        for (int c = 0; c < 4; c++) {
            int e = 4*v + c, i = e >> 3, j = e & 7;
            if (i >= j) Pt[i*(i+1)/2 + j] = vals[c];
        }
    }

    // ---- new_state = F @ state ----
    float ns[8];
    #pragma unroll
    for (int i = 0; i < 8; i++) {
        float a = 0.f;
        #pragma unroll
        for (int j = 0; j < 8; j++) a += Fm[i*8+j] * st[j];
        ns[i] = a;
    }

    // ---- P' = F P F^T (column-strip, lower tri) ----
    float Pp[36];
    #pragma unroll
    for (int l = 0; l < 8; l++) {
        float g[8];
        #pragma unroll
        for (int j = 0; j < 8; j++) {
            float a = 0.f;
            #pragma unroll
            for (int k = 0; k < 8; k++) a += psym(Pt, j, k) * Fm[l*8+k];
            g[j] = a;
        }
        #pragma unroll
        for (int i = l; i < 8; i++) {
            float a = 0.f;
            #pragma unroll
            for (int j = 0; j < 8; j++) a += Fm[i*8+j] * g[j];
            Pp[i*(i+1)/2 + l] = a;
        }
    }
    // Fm, Pt dead.

    // ---- P' += Q = Lq Lq^T ----
    {
        float Lq[36];
        #pragma unroll
        for (int v = 0; v < 9; v++) {
            float4 x = s4m[1376 + lane * 9 + v];
            Lq[4*v+0] = x.x; Lq[4*v+1] = x.y; Lq[4*v+2] = x.z; Lq[4*v+3] = x.w;
        }
        #pragma unroll
        for (int i = 0; i < 8; i++) {
            #pragma unroll
            for (int l = 0; l <= i; l++) {
                float a = Pp[i*(i+1)/2 + l];
                #pragma unroll
                for (int k = 0; k <= l; k++)
                    a += Lq[i*(i+1)/2 + k] * Lq[l*(l+1)/2 + k];
                Pp[i*(i+1)/2 + l] = a;
            }
        }
    }

    // ---- H; prediction & residual ----
    float Hm[32];
    #pragma unroll
    for (int v = 0; v < 8; v++) {
        float4 x = s4m[1088 + lane * 9 + v];
        Hm[4*v+0] = x.x; Hm[4*v+1] = x.y; Hm[4*v+2] = x.z; Hm[4*v+3] = x.w;
    }
    float pred[4], res[4];
    #pragma unroll
    for (int i = 0; i < 4; i++) {
        float a = 0.f;
        #pragma unroll
        for (int j = 0; j < 8; j++) a += Hm[i*8+j] * ns[j];
        pred[i] = a;
        res[i] = mea[i] - a;
    }

    // ---- PHt = P' @ H^T ----
    float PHt[32];
    #pragma unroll
    for (int i = 0; i < 8; i++) {
        #pragma unroll
        for (int j = 0; j < 4; j++) {
            float a = 0.f;
            #pragma unroll
            for (int k = 0; k < 8; k++) a += psym(Pp, i, k) * Hm[j*8+k];
            PHt[i*4+j] = a;
        }
    }

    // ---- S = H @ PHt + R ----
    float A[16];
    {
        float Lr[10];
        const float2* s2 = reinterpret_cast<const float2*>(sm);
        #pragma unroll
        for (int v = 0; v < 5; v++) {
            float2 x = s2[3328 + lane * 5 + v];
            Lr[2*v] = x.x; Lr[2*v+1] = x.y;
        }
        #pragma unroll
        for (int i = 0; i < 4; i++) {
            #pragma unroll
            for (int j = 0; j < 4; j++) {
                float a = 0.f;
                #pragma unroll
                for (int k = 0; k <= ((i < j) ? i : j); k++)
                    a += Lr[i*(i+1)/2 + k] * Lr[j*(j+1)/2 + k];
                #pragma unroll
                for (int k = 0; k < 8; k++) a += Hm[i*8+k] * PHt[k*4+j];
                A[i*4+j] = a;
            }
        }
    }

    // ---- Gauss-Jordan solve S X = [PHt^T | res] ----
    float Rh[36];
    #pragma unroll
    for (int r = 0; r < 4; r++) {
        #pragma unroll
        for (int c = 0; c < 8; c++) Rh[r*9+c] = PHt[c*4+r];
        Rh[r*9+8] = res[r];
    }
    #pragma unroll
    for (int c = 0; c < 4; c++) {
        float inv = 1.0f / A[c*4+c];
        #pragma unroll
        for (int j = 0; j < 4; j++) A[c*4+j] *= inv;
        #pragma unroll
        for (int j = 0; j < 9; j++) Rh[c*9+j] *= inv;
        #pragma unroll
        for (int r = 0; r < 4; r++) {
            if (r == c) continue;
            float f = A[r*4+c];
            #pragma unroll
            for (int j = 0; j < 4; j++) A[r*4+j] -= f * A[c*4+j];
            #pragma unroll
            for (int j = 0; j < 9; j++) Rh[r*9+j] -= f * Rh[c*9+j];
        }
    }

    // ---- upd_state ----
    float us[8];
    #pragma unroll
    for (int i = 0; i < 8; i++) {
        float a = ns[i];
        #pragma unroll
        for (int j = 0; j < 4; j++) a += PHt[i*4+j] * Rh[j*9+8];
        us[i] = a;
    }

    // ---- small outputs: direct coalesced STG ----
    reinterpret_cast<float4*>(o_pred)[b] = make_float4(pred[0], pred[1], pred[2], pred[3]);
    {
        float4* s4o = reinterpret_cast<float4*>(o_state) + (size_t)b * 2;
        s4o[0] = make_float4(us[0], us[1], us[2], us[3]);
        s4o[1] = make_float4(us[4], us[5], us[6], us[7]);
    }

    // ---- upd_cov = P' - PHt X (tri), write full rows to padded F region ----
    float UC[36];
    #pragma unroll
    for (int i = 0; i < 8; i++) {
        #pragma unroll
        for (int l = 0; l <= i; l++) {
            float a = Pp[i*(i+1)/2 + l];
            #pragma unroll
            for (int j = 0; j < 4; j++) a -= PHt[i*4+j] * Rh[j*9+l];
            UC[i*(i+1)/2 + l] = a;
        }
    }
    #pragma unroll
    for (int v = 0; v < 16; v++) {
        int e = 4*v;
        s4m[lane * 17 + v] = make_float4(
            psym(UC, (e+0) >> 3, (e+0) & 7),
            psym(UC, (e+1) >> 3, (e+1) & 7),
            psym(UC, (e+2) >> 3, (e+2) & 7),
            psym(UC, (e+3) >> 3, (e+3) & 7));
    }
    __syncwarp();

    // compress padded (17) -> linear (16) in place, then bulk store
    {
        float4 t[8];
        #pragma unroll
        for (int k = 0; k < 8; k++) {
            int g = lane + 32*k;
            t[k] = s4m[(g >> 4) * 17 + (g & 15)];
        }
        __syncwarp();
        #pragma unroll
        for (int k = 0; k < 8; k++) s4m[lane + 32*k] = t[k];
        __syncwarp();
        #pragma unroll
        for (int k = 0; k < 8; k++) {
            int g = 256 + lane + 32*k;
            t[k] = s4m[(g >> 4) * 17 + (g & 15)];
        }
        __syncwarp();
        #pragma unroll
        for (int k = 0; k < 8; k++) s4m[256 + lane + 32*k] = t[k];
        __syncwarp();
    }
    asm volatile("fence.proxy.async.shared::cta;" ::: "memory");
    if (lane == 0) {
        bulk_s2g(o_cov + (size_t)wb * 64, smb + OFF_F * 4, 8192);
        asm volatile("cp.async.bulk.commit_group;" ::: "memory");
        asm volatile("cp.async.bulk.wait_group 0;" ::: "memory");
    }
}

extern "C" void kernel_launch(void* const* d_in, const int* in_sizes, int n_in,
                              void* d_out, int out_size)
{
    const float* g_meas = (const float*)d_in[0];
    const float* g_state = (const float*)d_in[1];
    const float* g_cov  = (const float*)d_in[2];
    const float* g_F    = (const float*)d_in[3];
    const float* g_H    = (const float*)d_in[4];
    const float* g_pn   = (const float*)d_in[5];
    const float* g_mn   = (const float*)d_in[6];

    int B = in_sizes[0] / 4;   // measurement is (B, 4)

    float* o_pred  = (float*)d_out;
    float* o_state = o_pred + (size_t)B * 4;
    float* o_cov   = o_state + (size_t)B * 8;

    int blocks = (B + 31) / 32;
    ekf_kernel<<<blocks, 32>>>(g_meas, g_state, g_cov, g_F, g_H, g_pn, g_mn,
                               o_pred, o_state, o_cov, B);
}

// round 5
// speedup vs baseline: 1.1467x; 1.0046x over previous
#include <cuda_runtime.h>

// EKF cell: B=262144, N=8, M=4. One thread per batch, one warp per 32-batch CTA.
// Round-4: all strided global traffic replaced by cp.async.bulk DMA into smem
// (loads) and out of smem (cov store), with in-place pad-repack (stride 16->17
// float4) so smem->register transposes are bank-conflict-free with static
// register indexing.

#define OFF_F   0        // 2176 floats (544 f4): F, padded stride 17 f4
#define OFF_P   2176     // 2176 floats: state_cov, padded stride 17 f4
#define OFF_H   4352     // 1152 floats (288 f4): H, padded stride 9 f4
#define OFF_PN  5504     // 1152 floats: process noise, natural stride 9 f4
#define OFF_MN  6656     // 320 floats: measurement noise, natural stride 5 f2
#define OFF_MB  6976     // mbarrier (8B)
#define SM_FLOATS 6980
#define TX_BYTES 26368u  // 8192+8192+4096+4608+1280

__device__ __forceinline__ float psym(const float* t, int i, int j) {
    return (i >= j) ? t[i*(i+1)/2 + j] : t[j*(j+1)/2 + i];
}

__device__ __forceinline__ unsigned sptr(const void* p) {
    return (unsigned)__cvta_generic_to_shared(p);
}

__device__ __forceinline__ void bulk_g2s(unsigned dst, const void* src,
                                         unsigned bytes, unsigned mbar) {
    asm volatile(
        "cp.async.bulk.shared::cluster.global.mbarrier::complete_tx::bytes [%0], [%1], %2, [%3];"
        :: "r"(dst), "l"(src), "r"(bytes), "r"(mbar) : "memory");
}

__device__ __forceinline__ void bulk_s2g(void* dst, unsigned src, unsigned bytes) {
    asm volatile(
        "cp.async.bulk.global.shared::cta.bulk_group [%0], [%1], %2;"
        :: "l"(dst), "r"(src), "r"(bytes) : "memory");
}

__global__ __launch_bounds__(32, 8) void ekf_kernel(
    const float* __restrict__ g_meas,
    const float* __restrict__ g_state,
    const float* __restrict__ g_cov,
    const float* __restrict__ g_F,
    const float* __restrict__ g_H,
    const float* __restrict__ g_pn,
    const float* __restrict__ g_mn,
    float* __restrict__ o_pred,
    float* __restrict__ o_state,
    float* __restrict__ o_cov,
    int B)
{
    __shared__ __align__(16) float sm[SM_FLOATS];
    float4* s4m = reinterpret_cast<float4*>(sm);

    const int lane = threadIdx.x;
    int wb = blockIdx.x * 32;
    if (wb + 32 > B) wb = B - 32;   // clamp: duplicate identical work, in-bounds
    const int b = wb + lane;

    const unsigned smb  = sptr(sm);
    const unsigned mbar = smb + OFF_MB * 4;

    // ---------- bulk DMA loads ----------
    if (lane == 0) {
        asm volatile("mbarrier.init.shared.b64 [%0], 1;" :: "r"(mbar) : "memory");
    }
    __syncwarp();
    if (lane == 0) {
        asm volatile("fence.proxy.async.shared::cta;" ::: "memory");
        asm volatile("mbarrier.arrive.expect_tx.shared.b64 _, [%0], %1;"
                     :: "r"(mbar), "r"(TX_BYTES) : "memory");
        bulk_g2s(smb + OFF_F  * 4, g_F   + (size_t)wb * 64, 8192, mbar);
        bulk_g2s(smb + OFF_P  * 4, g_cov + (size_t)wb * 64, 8192, mbar);
        bulk_g2s(smb + OFF_H  * 4, g_H   + (size_t)wb * 32, 4096, mbar);
        bulk_g2s(smb + OFF_PN * 4, g_pn  + (size_t)wb * 36, 4608, mbar);
        bulk_g2s(smb + OFF_MN * 4, g_mn  + (size_t)wb * 10, 1280, mbar);
    }

    // overlap the DMA with the (already coalesced-enough) small direct loads
    float mea[4], st[8];
    {
        float4 mv = reinterpret_cast<const float4*>(g_meas)[b];
        mea[0] = mv.x; mea[1] = mv.y; mea[2] = mv.z; mea[3] = mv.w;
        const float4* s4 = reinterpret_cast<const float4*>(g_state) + (size_t)b * 2;
        float4 a = s4[0], c = s4[1];
        st[0]=a.x; st[1]=a.y; st[2]=a.z; st[3]=a.w;
        st[4]=c.x; st[5]=c.y; st[6]=c.z; st[7]=c.w;
    }

    // wait for DMA
    {
        asm volatile(
            "{\n\t"
            ".reg .pred P;\n"
            "W%=:\n\t"
            "mbarrier.try_wait.parity.shared.b64 P, [%0], 0;\n\t"
            "@!P bra W%=;\n\t"
            "}"
            :: "r"(mbar) : "memory");
    }
    __syncwarp();

    // ---------- in-place pad-repack: F and P, stride 16 -> 17 float4 ----------
    #pragma unroll
    for (int base = 544; base >= 0; base -= 544) {   // base 544 = P, base 0 = F
        float4 t[8];
        // pass A: batches 16..31
        #pragma unroll
        for (int k = 0; k < 8; k++) t[k] = s4m[base + 256 + lane + 32*k];
        __syncwarp();
        #pragma unroll
        for (int k = 0; k < 8; k++) {
            int g = 256 + lane + 32*k;
            s4m[base + (g >> 4) * 17 + (g & 15)] = t[k];
        }
        __syncwarp();
        // pass B: batches 0..15
        #pragma unroll
        for (int k = 0; k < 8; k++) t[k] = s4m[base + lane + 32*k];
        __syncwarp();
        #pragma unroll
        for (int k = 0; k < 8; k++) {
            int g = lane + 32*k;
            s4m[base + (g >> 4) * 17 + (g & 15)] = t[k];
        }
        __syncwarp();
    }
    // H: stride 8 -> 9 float4 (base f4 = 1088)
    {
        float4 t[4];
        #pragma unroll
        for (int k = 0; k < 4; k++) t[k] = s4m[1088 + 128 + lane + 32*k];
        __syncwarp();
        #pragma unroll
        for (int k = 0; k < 4; k++) {
            int g = 128 + lane + 32*k;
            s4m[1088 + (g >> 3) * 9 + (g & 7)] = t[k];
        }
        __syncwarp();
        #pragma unroll
        for (int k = 0; k < 4; k++) t[k] = s4m[1088 + lane + 32*k];
        __syncwarp();
        #pragma unroll
        for (int k = 0; k < 4; k++) {
            int g = lane + 32*k;
            s4m[1088 + (g >> 3) * 9 + (g & 7)] = t[k];
        }
        __syncwarp();
    }

    // ---------- unpack F (64) and P (tri 36); banks conflict-free ----------
    float Fm[64];
    #pragma unroll
    for (int v = 0; v < 16; v++) {
        float4 x = s4m[lane * 17 + v];
        Fm[4*v+0] = x.x; Fm[4*v+1] = x.y; Fm[4*v+2] = x.z; Fm[4*v+3] = x.w;
    }
    float Pt[36];
    #pragma unroll
    for (int v = 0; v < 16; v++) {
        float4 x = s4m[544 + lane * 17 + v];
        float vals[4] = {x.x, x.y, x.z, x.w};
        #pragma unroll
        for (int c = 0; c < 4; c++) {
            int e = 4*v + c, i = e >> 3, j = e & 7;
            if (i >= j) Pt[i*(i+1)/2 + j] = vals[c];
        }
    }

    // ---- new_state = F @ state ----
    float ns[8];
    #pragma unroll
    for (int i = 0; i < 8; i++) {
        float a = 0.f;
        #pragma unroll
        for (int j = 0; j < 8; j++) a += Fm[i*8+j] * st[j];
        ns[i] = a;
    }

    // ---- P' = F P F^T (column-strip, lower tri) ----
    float Pp[36];
    #pragma unroll
    for (int l = 0; l < 8; l++) {
        float g[8];
        #pragma unroll
        for (int j = 0; j < 8; j++) {
            float a = 0.f;
            #pragma unroll
            for (int k = 0; k < 8; k++) a += psym(Pt, j, k) * Fm[l*8+k];
            g[j] = a;
        }
        #pragma unroll
        for (int i = l; i < 8; i++) {
            float a = 0.f;
            #pragma unroll
            for (int j = 0; j < 8; j++) a += Fm[i*8+j] * g[j];
            Pp[i*(i+1)/2 + l] = a;
        }
    }
    // Fm, Pt dead.

    // ---- P' += Q = Lq Lq^T ----
    {
        float Lq[36];
        #pragma unroll
        for (int v = 0; v < 9; v++) {
            float4 x = s4m[1376 + lane * 9 + v];
            Lq[4*v+0] = x.x; Lq[4*v+1] = x.y; Lq[4*v+2] = x.z; Lq[4*v+3] = x.w;
        }
        #pragma unroll
        for (int i = 0; i < 8; i++) {
            #pragma unroll
            for (int l = 0; l <= i; l++) {
                float a = Pp[i*(i+1)/2 + l];
                #pragma unroll
                for (int k = 0; k <= l; k++)
                    a += Lq[i*(i+1)/2 + k] * Lq[l*(l+1)/2 + k];
                Pp[i*(i+1)/2 + l] = a;
            }
        }
    }

    // ---- H; prediction & residual ----
    float Hm[32];
    #pragma unroll
    for (int v = 0; v < 8; v++) {
        float4 x = s4m[1088 + lane * 9 + v];
        Hm[4*v+0] = x.x; Hm[4*v+1] = x.y; Hm[4*v+2] = x.z; Hm[4*v+3] = x.w;
    }
    float pred[4], res[4];
    #pragma unroll
    for (int i = 0; i < 4; i++) {
        float a = 0.f;
        #pragma unroll
        for (int j = 0; j < 8; j++) a += Hm[i*8+j] * ns[j];
        pred[i] = a;
        res[i] = mea[i] - a;
    }

    // ---- PHt = P' @ H^T ----
    float PHt[32];
    #pragma unroll
    for (int i = 0; i < 8; i++) {
        #pragma unroll
        for (int j = 0; j < 4; j++) {
            float a = 0.f;
            #pragma unroll
            for (int k = 0; k < 8; k++) a += psym(Pp, i, k) * Hm[j*8+k];
            PHt[i*4+j] = a;
        }
    }

    // ---- S = H @ PHt + R ----
    float A[16];
    {
        float Lr[10];
        const float2* s2 = reinterpret_cast<const float2*>(sm);
        #pragma unroll
        for (int v = 0; v < 5; v++) {
            float2 x = s2[3328 + lane * 5 + v];
            Lr[2*v] = x.x; Lr[2*v+1] = x.y;
        }
        #pragma unroll
        for (int i = 0; i < 4; i++) {
            #pragma unroll
            for (int j = 0; j < 4; j++) {
                float a = 0.f;
                #pragma unroll
                for (int k = 0; k <= ((i < j) ? i : j); k++)
                    a += Lr[i*(i+1)/2 + k] * Lr[j*(j+1)/2 + k];
                #pragma unroll
                for (int k = 0; k < 8; k++) a += Hm[i*8+k] * PHt[k*4+j];
                A[i*4+j] = a;
            }
        }
    }

    // ---- Gauss-Jordan solve S X = [PHt^T | res] ----
    float Rh[36];
    #pragma unroll
    for (int r = 0; r < 4; r++) {
        #pragma unroll
        for (int c = 0; c < 8; c++) Rh[r*9+c] = PHt[c*4+r];
        Rh[r*9+8] = res[r];
    }
    #pragma unroll
    for (int c = 0; c < 4; c++) {
        float inv = 1.0f / A[c*4+c];
        #pragma unroll
        for (int j = 0; j < 4; j++) A[c*4+j] *= inv;
        #pragma unroll
        for (int j = 0; j < 9; j++) Rh[c*9+j] *= inv;
        #pragma unroll
        for (int r = 0; r < 4; r++) {
            if (r == c) continue;
            float f = A[r*4+c];
            #pragma unroll
            for (int j = 0; j < 4; j++) A[r*4+j] -= f * A[c*4+j];
            #pragma unroll
            for (int j = 0; j < 9; j++) Rh[r*9+j] -= f * Rh[c*9+j];
        }
    }

    // ---- upd_state ----
    float us[8];
    #pragma unroll
    for (int i = 0; i < 8; i++) {
        float a = ns[i];
        #pragma unroll
        for (int j = 0; j < 4; j++) a += PHt[i*4+j] * Rh[j*9+8];
        us[i] = a;
    }

    // ---- small outputs: direct coalesced STG ----
    reinterpret_cast<float4*>(o_pred)[b] = make_float4(pred[0], pred[1], pred[2], pred[3]);
    {
        float4* s4o = reinterpret_cast<float4*>(o_state) + (size_t)b * 2;
        s4o[0] = make_float4(us[0], us[1], us[2], us[3]);
        s4o[1] = make_float4(us[4], us[5], us[6], us[7]);
    }

    // ---- upd_cov = P' - PHt X (tri), write full rows to padded F region ----
    float UC[36];
    #pragma unroll
    for (int i = 0; i < 8; i++) {
        #pragma unroll
        for (int l = 0; l <= i; l++) {
            float a = Pp[i*(i+1)/2 + l];
            #pragma unroll
            for (int j = 0; j < 4; j++) a -= PHt[i*4+j] * Rh[j*9+l];
            UC[i*(i+1)/2 + l] = a;
        }
    }
    #pragma unroll
    for (int v = 0; v < 16; v++) {
        int e = 4*v;
        s4m[lane * 17 + v] = make_float4(
            psym(UC, (e+0) >> 3, (e+0) & 7),
            psym(UC, (e+1) >> 3, (e+1) & 7),
            psym(UC, (e+2) >> 3, (e+2) & 7),
            psym(UC, (e+3) >> 3, (e+3) & 7));
    }
    __syncwarp();

    // compress padded (17) -> linear (16) in place, then bulk store
    {
        float4 t[8];
        #pragma unroll
        for (int k = 0; k < 8; k++) {
            int g = lane + 32*k;
            t[k] = s4m[(g >> 4) * 17 + (g & 15)];
        }
        __syncwarp();
        #pragma unroll
        for (int k = 0; k < 8; k++) s4m[lane + 32*k] = t[k];
        __syncwarp();
        #pragma unroll
        for (int k = 0; k < 8; k++) {
            int g = 256 + lane + 32*k;
            t[k] = s4m[(g >> 4) * 17 + (g & 15)];
        }
        __syncwarp();
        #pragma unroll
        for (int k = 0; k < 8; k++) s4m[256 + lane + 32*k] = t[k];
        __syncwarp();
    }
    asm volatile("fence.proxy.async.shared::cta;" ::: "memory");
    if (lane == 0) {
        bulk_s2g(o_cov + (size_t)wb * 64, smb + OFF_F * 4, 8192);
        asm volatile("cp.async.bulk.commit_group;" ::: "memory");
        asm volatile("cp.async.bulk.wait_group 0;" ::: "memory");
    }
}

extern "C" void kernel_launch(void* const* d_in, const int* in_sizes, int n_in,
                              void* d_out, int out_size)
{
    const float* g_meas = (const float*)d_in[0];
    const float* g_state = (const float*)d_in[1];
    const float* g_cov  = (const float*)d_in[2];
    const float* g_F    = (const float*)d_in[3];
    const float* g_H    = (const float*)d_in[4];
    const float* g_pn   = (const float*)d_in[5];
    const float* g_mn   = (const float*)d_in[6];

    int B = in_sizes[0] / 4;   // measurement is (B, 4)

    float* o_pred  = (float*)d_out;
    float* o_state = o_pred + (size_t)B * 4;
    float* o_cov   = o_state + (size_t)B * 8;

    int blocks = (B + 31) / 32;
    ekf_kernel<<<blocks, 32>>>(g_meas, g_state, g_cov, g_F, g_H, g_pn, g_mn,
                               o_pred, o_state, o_cov, B);
}

// round 7
// speedup vs baseline: 1.2737x; 1.1107x over previous
#include <cuda_runtime.h>

// EKF cell: B=262144, N=8, M=4. One thread/batch, one warp/CTA (32 batches).
// Round-7 (= round-6 fixed): two-phase TMA with smem time-multiplexing
// (high-water 17.4KB/CTA) + 170-reg cap -> 12 warps/SM.
// Phase-2 layout fix: pn occupies f4 [288,576), mn at f4 [576,656) -- the
// round-6 failure was mn's TMA landing inside pn (float-vs-float4 unit slip).
// Phase-2 extends into the dead P padded region (Pt already in registers).

#define OFF_P_F4   544       // P padded region base (f4)
#define OFF_MB_FLT 4352      // mbarrier (float offset, 16B aligned)
#define SM_FLOATS  4356
#define TX1 16384u           // F 8192 + P 8192
#define TX2 9984u            // H 4096 + pn 4608 + mn 1280
#define PN_F4 288            // pn base (f4): 288..575
#define MN_F4 576            // mn base (f4): 576..655

__device__ __forceinline__ float psym(const float* t, int i, int j) {
    return (i >= j) ? t[i*(i+1)/2 + j] : t[j*(j+1)/2 + i];
}

__device__ __forceinline__ unsigned sptr(const void* p) {
    return (unsigned)__cvta_generic_to_shared(p);
}

__device__ __forceinline__ void bulk_g2s(unsigned dst, const void* src,
                                         unsigned bytes, unsigned mbar) {
    asm volatile(
        "cp.async.bulk.shared::cluster.global.mbarrier::complete_tx::bytes [%0], [%1], %2, [%3];"
        :: "r"(dst), "l"(src), "r"(bytes), "r"(mbar) : "memory");
}

__device__ __forceinline__ void bulk_s2g(void* dst, unsigned src, unsigned bytes) {
    asm volatile(
        "cp.async.bulk.global.shared::cta.bulk_group [%0], [%1], %2;"
        :: "l"(dst), "r"(src), "r"(bytes) : "memory");
}

__device__ __forceinline__ void mbar_wait(unsigned mbar, int parity) {
    asm volatile(
        "{\n\t"
        ".reg .pred P;\n"
        "W%=:\n\t"
        "mbarrier.try_wait.parity.shared.b64 P, [%0], %1;\n\t"
        "@!P bra W%=;\n\t"
        "}"
        :: "r"(mbar), "r"(parity) : "memory");
}

__global__ __launch_bounds__(32, 12) void ekf_kernel(
    const float* __restrict__ g_meas,
    const float* __restrict__ g_state,
    const float* __restrict__ g_cov,
    const float* __restrict__ g_F,
    const float* __restrict__ g_H,
    const float* __restrict__ g_pn,
    const float* __restrict__ g_mn,
    float* __restrict__ o_pred,
    float* __restrict__ o_state,
    float* __restrict__ o_cov,
    int B)
{
    __shared__ __align__(16) float sm[SM_FLOATS];
    float4* s4m = reinterpret_cast<float4*>(sm);

    const int lane = threadIdx.x;
    int wb = blockIdx.x * 32;
    if (wb + 32 > B) wb = B - 32;   // clamp tail: duplicate identical work
    const int b = wb + lane;

    const unsigned smb  = sptr(sm);
    const unsigned mbar = smb + OFF_MB_FLT * 4;

    // ---------- phase 1: TMA F + P ----------
    if (lane == 0) {
        asm volatile("mbarrier.init.shared.b64 [%0], 1;" :: "r"(mbar) : "memory");
    }
    __syncwarp();
    if (lane == 0) {
        asm volatile("fence.proxy.async.shared::cta;" ::: "memory");
        asm volatile("mbarrier.arrive.expect_tx.shared.b64 _, [%0], %1;"
                     :: "r"(mbar), "r"(TX1) : "memory");
        bulk_g2s(smb,                  g_F   + (size_t)wb * 64, 8192, mbar);
        bulk_g2s(smb + OFF_P_F4 * 16,  g_cov + (size_t)wb * 64, 8192, mbar);
    }

    // overlap: small direct loads
    float mea[4], st[8];
    {
        float4 mv = reinterpret_cast<const float4*>(g_meas)[b];
        mea[0] = mv.x; mea[1] = mv.y; mea[2] = mv.z; mea[3] = mv.w;
        const float4* s4 = reinterpret_cast<const float4*>(g_state) + (size_t)b * 2;
        float4 a = s4[0], c = s4[1];
        st[0]=a.x; st[1]=a.y; st[2]=a.z; st[3]=a.w;
        st[4]=c.x; st[5]=c.y; st[6]=c.z; st[7]=c.w;
    }

    mbar_wait(mbar, 0);
    __syncwarp();

    // ---------- pad-repack F and P: stride 16 -> 17 f4 (in place) ----------
    #pragma unroll
    for (int base = OFF_P_F4; base >= 0; base -= OFF_P_F4) {  // P then F
        float4 t[8];
        #pragma unroll
        for (int k = 0; k < 8; k++) t[k] = s4m[base + 256 + lane + 32*k];
        __syncwarp();
        #pragma unroll
        for (int k = 0; k < 8; k++) {
            int g = 256 + lane + 32*k;
            s4m[base + (g >> 4) * 17 + (g & 15)] = t[k];
        }
        __syncwarp();
        #pragma unroll
        for (int k = 0; k < 8; k++) t[k] = s4m[base + lane + 32*k];
        __syncwarp();
        #pragma unroll
        for (int k = 0; k < 8; k++) {
            int g = lane + 32*k;
            s4m[base + (g >> 4) * 17 + (g & 15)] = t[k];
        }
        __syncwarp();
    }

    // ---------- unpack F (64 regs) and P (tri 36 regs) ----------
    float Fm[64];
    #pragma unroll
    for (int v = 0; v < 16; v++) {
        float4 x = s4m[lane * 17 + v];
        Fm[4*v+0] = x.x; Fm[4*v+1] = x.y; Fm[4*v+2] = x.z; Fm[4*v+3] = x.w;
    }
    float Pt[36];
    #pragma unroll
    for (int v = 0; v < 16; v++) {
        float4 x = s4m[OFF_P_F4 + lane * 17 + v];
        float vals[4] = {x.x, x.y, x.z, x.w};
        #pragma unroll
        for (int c = 0; c < 4; c++) {
            int e = 4*v + c, i = e >> 3, j = e & 7;
            if (i >= j) Pt[i*(i+1)/2 + j] = vals[c];
        }
    }
    __syncwarp();   // all lanes done reading F/P smem

    // ---------- phase 2: TMA H / pn / mn into now-dead smem ----------
    // H raw at f4 [0,256) -> repacked to [0,287); pn [288,576); mn [576,656).
    if (lane == 0) {
        asm volatile("fence.proxy.async.shared::cta;" ::: "memory");
        asm volatile("mbarrier.arrive.expect_tx.shared.b64 _, [%0], %1;"
                     :: "r"(mbar), "r"(TX2) : "memory");
        bulk_g2s(smb,              g_H  + (size_t)wb * 32, 4096, mbar);
        bulk_g2s(smb + PN_F4 * 16, g_pn + (size_t)wb * 36, 4608, mbar);
        bulk_g2s(smb + MN_F4 * 16, g_mn + (size_t)wb * 10, 1280, mbar);
    }

    // ---- compute overlapped with phase-2 TMA ----
    float ns[8];
    #pragma unroll
    for (int i = 0; i < 8; i++) {
        float a = 0.f;
        #pragma unroll
        for (int j = 0; j < 8; j++) a += Fm[i*8+j] * st[j];
        ns[i] = a;
    }
    // P' = F P F^T (column-strip, lower tri)
    float Pp[36];
    #pragma unroll
    for (int l = 0; l < 8; l++) {
        float g[8];
        #pragma unroll
        for (int j = 0; j < 8; j++) {
            float a = 0.f;
            #pragma unroll
            for (int k = 0; k < 8; k++) a += psym(Pt, j, k) * Fm[l*8+k];
            g[j] = a;
        }
        #pragma unroll
        for (int i = l; i < 8; i++) {
            float a = 0.f;
            #pragma unroll
            for (int j = 0; j < 8; j++) a += Fm[i*8+j] * g[j];
            Pp[i*(i+1)/2 + l] = a;
        }
    }
    // Fm, Pt dead.

    mbar_wait(mbar, 1);
    __syncwarp();

    // ---- repack H: stride 8 -> 9 f4 (in place, top half first) ----
    {
        float4 t[4];
        #pragma unroll
        for (int k = 0; k < 4; k++) t[k] = s4m[128 + lane + 32*k];
        __syncwarp();
        #pragma unroll
        for (int k = 0; k < 4; k++) {
            int g = 128 + lane + 32*k;
            s4m[(g >> 3) * 9 + (g & 7)] = t[k];
        }
        __syncwarp();
        #pragma unroll
        for (int k = 0; k < 4; k++) t[k] = s4m[lane + 32*k];
        __syncwarp();
        #pragma unroll
        for (int k = 0; k < 4; k++) {
            int g = lane + 32*k;
            s4m[(g >> 3) * 9 + (g & 7)] = t[k];
        }
        __syncwarp();
    }

    // ---- P' += Q = Lq Lq^T ----
    {
        float Lq[36];
        #pragma unroll
        for (int v = 0; v < 9; v++) {
            float4 x = s4m[PN_F4 + lane * 9 + v];
            Lq[4*v+0] = x.x; Lq[4*v+1] = x.y; Lq[4*v+2] = x.z; Lq[4*v+3] = x.w;
        }
        #pragma unroll
        for (int i = 0; i < 8; i++) {
            #pragma unroll
            for (int l = 0; l <= i; l++) {
                float a = Pp[i*(i+1)/2 + l];
                #pragma unroll
                for (int k = 0; k <= l; k++)
                    a += Lq[i*(i+1)/2 + k] * Lq[l*(l+1)/2 + k];
                Pp[i*(i+1)/2 + l] = a;
            }
        }
    }

    // ---- H; prediction & residual ----
    float Hm[32];
    #pragma unroll
    for (int v = 0; v < 8; v++) {
        float4 x = s4m[lane * 9 + v];
        Hm[4*v+0] = x.x; Hm[4*v+1] = x.y; Hm[4*v+2] = x.z; Hm[4*v+3] = x.w;
    }
    float pred[4], res[4];
    #pragma unroll
    for (int i = 0; i < 4; i++) {
        float a = 0.f;
        #pragma unroll
        for (int j = 0; j < 8; j++) a += Hm[i*8+j] * ns[j];
        pred[i] = a;
        res[i] = mea[i] - a;
    }

    // ---- PHt = P' @ H^T ----
    float PHt[32];
    #pragma unroll
    for (int i = 0; i < 8; i++) {
        #pragma unroll
        for (int j = 0; j < 4; j++) {
            float a = 0.f;
            #pragma unroll
            for (int k = 0; k < 8; k++) a += psym(Pp, i, k) * Hm[j*8+k];
            PHt[i*4+j] = a;
        }
    }

    // ---- S = H @ PHt + R  (mn at f4 576 = float2 index 1152) ----
    float A[16];
    {
        float Lr[10];
        const float2* s2 = reinterpret_cast<const float2*>(sm);
        #pragma unroll
        for (int v = 0; v < 5; v++) {
            float2 x = s2[1152 + lane * 5 + v];
            Lr[2*v] = x.x; Lr[2*v+1] = x.y;
        }
        #pragma unroll
        for (int i = 0; i < 4; i++) {
            #pragma unroll
            for (int j = 0; j < 4; j++) {
                float a = 0.f;
                #pragma unroll
                for (int k = 0; k <= ((i < j) ? i : j); k++)
                    a += Lr[i*(i+1)/2 + k] * Lr[j*(j+1)/2 + k];
                #pragma unroll
                for (int k = 0; k < 8; k++) a += Hm[i*8+k] * PHt[k*4+j];
                A[i*4+j] = a;
            }
        }
    }

    // ---- Gauss-Jordan solve S X = [PHt^T | res] ----
    float Rh[36];
    #pragma unroll
    for (int r = 0; r < 4; r++) {
        #pragma unroll
        for (int c = 0; c < 8; c++) Rh[r*9+c] = PHt[c*4+r];
        Rh[r*9+8] = res[r];
    }
    #pragma unroll
    for (int c = 0; c < 4; c++) {
        float inv = 1.0f / A[c*4+c];
        #pragma unroll
        for (int j = 0; j < 4; j++) A[c*4+j] *= inv;
        #pragma unroll
        for (int j = 0; j < 9; j++) Rh[c*9+j] *= inv;
        #pragma unroll
        for (int r = 0; r < 4; r++) {
            if (r == c) continue;
            float f = A[r*4+c];
            #pragma unroll
            for (int j = 0; j < 4; j++) A[r*4+j] -= f * A[c*4+j];
            #pragma unroll
            for (int j = 0; j < 9; j++) Rh[r*9+j] -= f * Rh[c*9+j];
        }
    }

    // ---- upd_state ----
    float us[8];
    #pragma unroll
    for (int i = 0; i < 8; i++) {
        float a = ns[i];
        #pragma unroll
        for (int j = 0; j < 4; j++) a += PHt[i*4+j] * Rh[j*9+8];
        us[i] = a;
    }

    // ---- small outputs: direct coalesced STG ----
    reinterpret_cast<float4*>(o_pred)[b] = make_float4(pred[0], pred[1], pred[2], pred[3]);
    {
        float4* s4o = reinterpret_cast<float4*>(o_state) + (size_t)b * 2;
        s4o[0] = make_float4(us[0], us[1], us[2], us[3]);
        s4o[1] = make_float4(us[4], us[5], us[6], us[7]);
    }

    // ---- upd_cov = P' - PHt X (tri); stage padded, compress, bulk store ----
    float UC[36];
    #pragma unroll
    for (int i = 0; i < 8; i++) {
        #pragma unroll
        for (int l = 0; l <= i; l++) {
            float a = Pp[i*(i+1)/2 + l];
            #pragma unroll
            for (int j = 0; j < 4; j++) a -= PHt[i*4+j] * Rh[j*9+l];
            UC[i*(i+1)/2 + l] = a;
        }
    }
    __syncwarp();   // all lanes done reading H/pn/mn smem
    #pragma unroll
    for (int v = 0; v < 16; v++) {
        int e = 4*v;
        s4m[lane * 17 + v] = make_float4(
            psym(UC, (e+0) >> 3, (e+0) & 7),
            psym(UC, (e+1) >> 3, (e+1) & 7),
            psym(UC, (e+2) >> 3, (e+2) & 7),
            psym(UC, (e+3) >> 3, (e+3) & 7));
    }
    __syncwarp();
    {
        float4 t[8];
        #pragma unroll
        for (int k = 0; k < 8; k++) {
            int g = lane + 32*k;
            t[k] = s4m[(g >> 4) * 17 + (g & 15)];
        }
        __syncwarp();
        #pragma unroll
        for (int k = 0; k < 8; k++) s4m[lane + 32*k] = t[k];
        __syncwarp();
        #pragma unroll
        for (int k = 0; k < 8; k++) {
            int g = 256 + lane + 32*k;
            t[k] = s4m[(g >> 4) * 17 + (g & 15)];
        }
        __syncwarp();
        #pragma unroll
        for (int k = 0; k < 8; k++) s4m[256 + lane + 32*k] = t[k];
        __syncwarp();
    }
    asm volatile("fence.proxy.async.shared::cta;" ::: "memory");
    if (lane == 0) {
        bulk_s2g(o_cov + (size_t)wb * 64, smb, 8192);
        asm volatile("cp.async.bulk.commit_group;" ::: "memory");
        asm volatile("cp.async.bulk.wait_group 0;" ::: "memory");
    }
}

extern "C" void kernel_launch(void* const* d_in, const int* in_sizes, int n_in,
                              void* d_out, int out_size)
{
    const float* g_meas = (const float*)d_in[0];
    const float* g_state = (const float*)d_in[1];
    const float* g_cov  = (const float*)d_in[2];
    const float* g_F    = (const float*)d_in[3];
    const float* g_H    = (const float*)d_in[4];
    const float* g_pn   = (const float*)d_in[5];
    const float* g_mn   = (const float*)d_in[6];

    int B = in_sizes[0] / 4;   // measurement is (B, 4)

    float* o_pred  = (float*)d_out;
    float* o_state = o_pred + (size_t)B * 4;
    float* o_cov   = o_state + (size_t)B * 8;

    int blocks = (B + 31) / 32;
    ekf_kernel<<<blocks, 32>>>(g_meas, g_state, g_cov, g_F, g_H, g_pn, g_mn,
                               o_pred, o_state, o_cov, B);
}